// round 2
// baseline (speedup 1.0000x reference)
#include <cuda_runtime.h>
#include <cuda_bf16.h>
#include <cstdint>

// ---------------- problem constants ----------------
#define NCOLS 8192
#define BLK   256
#define NBLK  16

// ---------------- tile config ----------------
#define BM 256      // rows per CTA = full diagonal block (X read exactly once)
#define BN 128      // output cols per CTA
#define KC 32       // K chunk
#define NCHUNK 8    // 256/32

// ---------------- SMEM layout (bytes, per stage) ----------------
// A: 256 rows x (32 bf16 + 4 pad) = 80B/row  -> conflict-free ldmatrix
// B:  32 rows x (128 bf16 + 4 pad) = 272B/row
#define A_ROW_B 80
#define B_ROW_B 272
#define OFF_A_HI 0
#define OFF_A_LO (256 * A_ROW_B)               // 20480
#define OFF_B_HI (2 * 256 * A_ROW_B)           // 40960
#define OFF_B_LO (OFF_B_HI + 32 * B_ROW_B)     // 49664
#define STAGE_B  (OFF_B_LO + 32 * B_ROW_B)     // 58368
#define SMEM_TOTAL (2 * STAGE_B)               // 116736

// ---------------- helpers ----------------
__device__ __forceinline__ uint32_t smem_u32(const void* p) {
    uint32_t a;
    asm("{ .reg .u64 t; cvta.to.shared.u64 t, %1; cvt.u32.u64 %0, t; }" : "=r"(a) : "l"(p));
    return a;
}

// round-to-nearest-even bf16 bits kept in fp32 position (low 16 zeroed)
__device__ __forceinline__ uint32_t rn_bf16_f32bits(float x) {
    uint32_t xb = __float_as_uint(x);
    return (xb + 0x7FFFu + ((xb >> 16) & 1u)) & 0xFFFF0000u;
}

// split two fp32 into packed bf16x2 hi and bf16x2 lo (x0 -> low half)
__device__ __forceinline__ void split_pair(float x0, float x1, uint32_t& hi, uint32_t& lo) {
    uint32_t r0 = rn_bf16_f32bits(x0);
    uint32_t r1 = rn_bf16_f32bits(x1);
    hi = (r0 >> 16) | r1;
    float e0 = x0 - __uint_as_float(r0);
    float e1 = x1 - __uint_as_float(r1);
    asm("cvt.rn.bf16x2.f32 %0, %1, %2;" : "=r"(lo) : "f"(e1), "f"(e0));
}

__device__ __forceinline__ void ldm_x4(uint32_t (&r)[4], uint32_t addr) {
    asm volatile("ldmatrix.sync.aligned.m8n8.x4.shared.b16 {%0,%1,%2,%3}, [%4];"
                 : "=r"(r[0]), "=r"(r[1]), "=r"(r[2]), "=r"(r[3]) : "r"(addr));
}

__device__ __forceinline__ void ldm_x2t(uint32_t (&r)[2], uint32_t addr) {
    asm volatile("ldmatrix.sync.aligned.m8n8.x2.trans.shared.b16 {%0,%1}, [%2];"
                 : "=r"(r[0]), "=r"(r[1]) : "r"(addr));
}

__device__ __forceinline__ void mma_bf16(float (&d)[4], const uint32_t (&a)[4],
                                         const uint32_t (&b)[2]) {
    asm volatile(
        "mma.sync.aligned.m16n8k16.row.col.f32.bf16.bf16.f32 "
        "{%0,%1,%2,%3}, {%4,%5,%6,%7}, {%8,%9}, {%0,%1,%2,%3};"
        : "+f"(d[0]), "+f"(d[1]), "+f"(d[2]), "+f"(d[3])
        : "r"(a[0]), "r"(a[1]), "r"(a[2]), "r"(a[3]), "r"(b[0]), "r"(b[1]));
}

// ---------------- kernel ----------------
__global__ void __launch_bounds__(256, 1)
blk_gemm(const float* __restrict__ X,   // [4096, 8192]
         const float* __restrict__ W,   // [16, 256, 256]
         float* __restrict__ out)       // [4096, 8192]
{
    extern __shared__ char smem[];
    const uint32_t sb = smem_u32(smem);
    const int tid  = threadIdx.x;
    const int lane = tid & 31;
    const int w    = tid >> 5;
    const int wm   = w & 3;        // M quadrant (64 rows)
    const int wn   = w >> 2;       // N half (64 cols)
    const int b    = blockIdx.x >> 6;
    const int nt   = blockIdx.x & 63;

    const float* Xb = X + (size_t)b * BLK * NCOLS + (size_t)nt * BN;
    const float* Wb = W + (size_t)b * (BLK * BLK);

    float acc[4][8][4];
    #pragma unroll
    for (int mi = 0; mi < 4; mi++)
        #pragma unroll
        for (int nj = 0; nj < 8; nj++)
            #pragma unroll
            for (int q = 0; q < 4; q++) acc[mi][nj][q] = 0.f;

    // global-load index mapping (coalesced)
    const int ar  = tid >> 4;   // A: base row 0..15 (+16*i), float2 at kpair
    const int akp = tid & 15;
    const int br  = tid >> 5;   // B: base row 0..7 (+8*i), float4 at 4*bc
    const int bc  = tid & 31;

    // prefetch registers
    float2 aR[16];
    float4 bR[4];
    #pragma unroll
    for (int i = 0; i < 16; i++)
        aR[i] = *(const float2*)(Wb + (size_t)(ar + 16 * i) * BLK + 2 * akp);
    #pragma unroll
    for (int i = 0; i < 4; i++)
        bR[i] = *(const float4*)(Xb + (size_t)(br + 8 * i) * NCOLS + 4 * bc);

    for (int c = 0; c < NCHUNK; c++) {
        char* stp = smem + (c & 1) * STAGE_B;

        // ---- convert + store A chunk (hi/lo) ----
        #pragma unroll
        for (int i = 0; i < 16; i++) {
            uint32_t hi, lo;
            split_pair(aR[i].x, aR[i].y, hi, lo);
            const int row = ar + 16 * i;
            *(uint32_t*)(stp + OFF_A_HI + row * A_ROW_B + akp * 4) = hi;
            *(uint32_t*)(stp + OFF_A_LO + row * A_ROW_B + akp * 4) = lo;
        }
        // ---- convert + store B chunk (hi/lo) ----
        #pragma unroll
        for (int i = 0; i < 4; i++) {
            uint32_t h0, l0, h1, l1;
            split_pair(bR[i].x, bR[i].y, h0, l0);
            split_pair(bR[i].z, bR[i].w, h1, l1);
            const int row = br + 8 * i;
            uint2 hv; hv.x = h0; hv.y = h1;
            uint2 lv; lv.x = l0; lv.y = l1;
            *(uint2*)(stp + OFF_B_HI + row * B_ROW_B + bc * 8) = hv;
            *(uint2*)(stp + OFF_B_LO + row * B_ROW_B + bc * 8) = lv;
        }
        // ---- prefetch next chunk (overlaps with MMA below) ----
        if (c < NCHUNK - 1) {
            #pragma unroll
            for (int i = 0; i < 16; i++)
                aR[i] = *(const float2*)(Wb + (size_t)(ar + 16 * i) * BLK +
                                         (c + 1) * KC + 2 * akp);
            #pragma unroll
            for (int i = 0; i < 4; i++)
                bR[i] = *(const float4*)(Xb + (size_t)((c + 1) * KC + br + 8 * i) * NCOLS +
                                         4 * bc);
        }
        __syncthreads();

        // ---- MMA on this stage: 3 bf16 passes, fp32 accumulate ----
        const uint32_t sa = sb + (c & 1) * STAGE_B;
        #pragma unroll
        for (int ki = 0; ki < 2; ki++) {
            const uint32_t a_off =
                (uint32_t)((wm * 64 + (lane & 15)) * A_ROW_B + (ki * 16 + (lane >> 4) * 8) * 2);
            const uint32_t b_off =
                (uint32_t)((ki * 16 + (lane & 15)) * B_ROW_B + (wn * 64) * 2);

            uint32_t Ah[4][4], Al[4][4], Bh[8][2], Bl[8][2];
            #pragma unroll
            for (int mi = 0; mi < 4; mi++)
                ldm_x4(Ah[mi], sa + OFF_A_HI + a_off + mi * 16 * A_ROW_B);
            #pragma unroll
            for (int nj = 0; nj < 8; nj++)
                ldm_x2t(Bh[nj], sa + OFF_B_HI + b_off + nj * 16);
            #pragma unroll
            for (int mi = 0; mi < 4; mi++)
                #pragma unroll
                for (int nj = 0; nj < 8; nj++)
                    mma_bf16(acc[mi][nj], Ah[mi], Bh[nj]);   // Ah x Bh

            #pragma unroll
            for (int nj = 0; nj < 8; nj++)
                ldm_x2t(Bl[nj], sa + OFF_B_LO + b_off + nj * 16);
            #pragma unroll
            for (int mi = 0; mi < 4; mi++)
                #pragma unroll
                for (int nj = 0; nj < 8; nj++)
                    mma_bf16(acc[mi][nj], Ah[mi], Bl[nj]);   // Ah x Bl

            #pragma unroll
            for (int mi = 0; mi < 4; mi++)
                ldm_x4(Al[mi], sa + OFF_A_LO + a_off + mi * 16 * A_ROW_B);
            #pragma unroll
            for (int mi = 0; mi < 4; mi++)
                #pragma unroll
                for (int nj = 0; nj < 8; nj++)
                    mma_bf16(acc[mi][nj], Al[mi], Bh[nj]);   // Al x Bh
        }
    }

    // ---- epilogue: registers -> global ----
    const int r0 = b * BLK + wm * 64 + (lane >> 2);
    const int c0 = nt * BN + wn * 64 + (lane & 3) * 2;
    #pragma unroll
    for (int mi = 0; mi < 4; mi++)
        #pragma unroll
        for (int nj = 0; nj < 8; nj++) {
            float2 v0; v0.x = acc[mi][nj][0]; v0.y = acc[mi][nj][1];
            float2 v1; v1.x = acc[mi][nj][2]; v1.y = acc[mi][nj][3];
            const size_t base = (size_t)(r0 + mi * 16) * NCOLS + (size_t)(c0 + nj * 8);
            *(float2*)(out + base) = v0;
            *(float2*)(out + base + (size_t)8 * NCOLS) = v1;
        }
}

// ---------------- launch ----------------
extern "C" void kernel_launch(void* const* d_in, const int* in_sizes, int n_in,
                              void* d_out, int out_size) {
    const float* X = (const float*)d_in[0];   // inp [4096, 8192]
    const float* W = (const float*)d_in[1];   // W   [16, 256, 256]
    float* out = (float*)d_out;

    cudaFuncSetAttribute(blk_gemm, cudaFuncAttributeMaxDynamicSharedMemorySize, SMEM_TOTAL);

    dim3 grid(NBLK * (NCOLS / BN));   // 16 * 64 = 1024
    blk_gemm<<<grid, 256, SMEM_TOTAL>>>(X, W, out);
}

// round 3
// speedup vs baseline: 1.1881x; 1.1881x over previous
#include <cuda_runtime.h>
#include <cuda_fp16.h>
#include <cstdint>

// ---------------- problem constants ----------------
#define NCOLS 8192
#define BLK   256
#define NBLK  16

// ---------------- tile config ----------------
#define BM 256      // rows per CTA = full diagonal block (X read exactly once)
#define BN 128      // output cols per CTA
#define KC 32       // K chunk
#define NCHUNK 8    // 256/32

// ---------------- SMEM layout (bytes, per stage) ----------------
// A_hi: 256 rows x (32 fp16 = 64B + 16B pad) = 80B/row
// B_hi/B_lo: 32 rows x (128 fp16 = 256B + 16B pad) = 272B/row
#define A_ROW_B 80
#define B_ROW_B 272
#define OFF_A_HI 0
#define OFF_B_HI (256 * A_ROW_B)               // 20480
#define OFF_B_LO (OFF_B_HI + 32 * B_ROW_B)     // 29184
#define STAGE_B  (OFF_B_LO + 32 * B_ROW_B)     // 37888
#define SMEM_TOTAL (2 * STAGE_B)               // 75776

// ---------------- helpers ----------------
__device__ __forceinline__ uint32_t smem_u32(const void* p) {
    uint32_t a;
    asm("{ .reg .u64 t; cvta.to.shared.u64 t, %1; cvt.u32.u64 %0, t; }" : "=r"(a) : "l"(p));
    return a;
}

// pack two fp32 -> fp16x2 (x0 in low half)
__device__ __forceinline__ uint32_t cvt_f16x2(float x0, float x1) {
    uint32_t r;
    asm("cvt.rn.f16x2.f32 %0, %1, %2;" : "=r"(r) : "f"(x1), "f"(x0));
    return r;
}

// split two fp32 into fp16x2 hi and fp16x2 lo residual
__device__ __forceinline__ void split2h(float x0, float x1, uint32_t& hi, uint32_t& lo) {
    asm("{\n\t"
        ".reg .b16 h0, h1;\n\t"
        ".reg .f32 f0, f1, e0, e1;\n\t"
        "cvt.rn.f16.f32 h0, %2;\n\t"
        "cvt.rn.f16.f32 h1, %3;\n\t"
        "mov.b32 %0, {h0, h1};\n\t"
        "cvt.f32.f16 f0, h0;\n\t"
        "cvt.f32.f16 f1, h1;\n\t"
        "sub.f32 e0, %2, f0;\n\t"
        "sub.f32 e1, %3, f1;\n\t"
        "cvt.rn.f16x2.f32 %1, e1, e0;\n\t"
        "}"
        : "=r"(hi), "=r"(lo) : "f"(x0), "f"(x1));
}

__device__ __forceinline__ void ldm_x4(uint32_t (&r)[4], uint32_t addr) {
    asm volatile("ldmatrix.sync.aligned.m8n8.x4.shared.b16 {%0,%1,%2,%3}, [%4];"
                 : "=r"(r[0]), "=r"(r[1]), "=r"(r[2]), "=r"(r[3]) : "r"(addr));
}

__device__ __forceinline__ void ldm_x2t(uint32_t (&r)[2], uint32_t addr) {
    asm volatile("ldmatrix.sync.aligned.m8n8.x2.trans.shared.b16 {%0,%1}, [%2];"
                 : "=r"(r[0]), "=r"(r[1]) : "r"(addr));
}

__device__ __forceinline__ void mma_f16(float (&d)[4], const uint32_t (&a)[4],
                                        const uint32_t (&b)[2]) {
    asm volatile(
        "mma.sync.aligned.m16n8k16.row.col.f32.f16.f16.f32 "
        "{%0,%1,%2,%3}, {%4,%5,%6,%7}, {%8,%9}, {%0,%1,%2,%3};"
        : "+f"(d[0]), "+f"(d[1]), "+f"(d[2]), "+f"(d[3])
        : "r"(a[0]), "r"(a[1]), "r"(a[2]), "r"(a[3]), "r"(b[0]), "r"(b[1]));
}

// ---------------- kernel ----------------
__global__ void __launch_bounds__(512, 1)
blk_gemm(const float* __restrict__ X,   // [4096, 8192]
         const float* __restrict__ W,   // [16, 256, 256]
         float* __restrict__ out)       // [4096, 8192]
{
    extern __shared__ char smem[];
    const uint32_t sb = smem_u32(smem);
    const int tid  = threadIdx.x;
    const int lane = tid & 31;
    const int w    = tid >> 5;     // 0..15
    const int wm   = w & 3;        // M quadrant (64 rows)
    const int wn   = w >> 2;       // N quarter  (32 cols)
    const int b    = blockIdx.x >> 6;
    const int nt   = blockIdx.x & 63;

    const float* Xb = X + (size_t)b * BLK * NCOLS + (size_t)nt * BN;
    const float* Wb = W + (size_t)b * (BLK * BLK);

    float acc[4][4][4];
    #pragma unroll
    for (int mi = 0; mi < 4; mi++)
        #pragma unroll
        for (int nj = 0; nj < 4; nj++)
            #pragma unroll
            for (int q = 0; q < 4; q++) acc[mi][nj][q] = 0.f;

    // global-load index mapping (coalesced)
    const int ar  = tid >> 4;   // A: base row 0..31 (+32*i), float2 at kpair
    const int akp = tid & 15;
    const int br  = tid >> 5;   // B: base row 0..15 (+16*i), float4 at 4*bc
    const int bc  = tid & 31;

    // B register prefetch (DRAM latency)
    float4 bR[2];
    #pragma unroll
    for (int i = 0; i < 2; i++)
        bR[i] = *(const float4*)(Xb + (size_t)(br + 16 * i) * NCOLS + 4 * bc);

    for (int c = 0; c < NCHUNK; c++) {
        char* stp = smem + (c & 1) * STAGE_B;

        // ---- A chunk: load from L2-resident W, round to fp16 hi, store ----
        #pragma unroll
        for (int i = 0; i < 8; i++) {
            const int row = ar + 32 * i;
            float2 av = *(const float2*)(Wb + (size_t)row * BLK + c * KC + 2 * akp);
            *(uint32_t*)(stp + OFF_A_HI + row * A_ROW_B + akp * 4) = cvt_f16x2(av.x, av.y);
        }
        // ---- B chunk: split prefetched fp32 into fp16 hi + lo, store ----
        #pragma unroll
        for (int i = 0; i < 2; i++) {
            uint32_t h0, l0, h1, l1;
            split2h(bR[i].x, bR[i].y, h0, l0);
            split2h(bR[i].z, bR[i].w, h1, l1);
            const int row = br + 16 * i;
            uint2 hv; hv.x = h0; hv.y = h1;
            uint2 lv; lv.x = l0; lv.y = l1;
            *(uint2*)(stp + OFF_B_HI + row * B_ROW_B + bc * 8) = hv;
            *(uint2*)(stp + OFF_B_LO + row * B_ROW_B + bc * 8) = lv;
        }
        // ---- prefetch next B chunk (overlaps with MMA below) ----
        if (c < NCHUNK - 1) {
            #pragma unroll
            for (int i = 0; i < 2; i++)
                bR[i] = *(const float4*)(Xb + (size_t)((c + 1) * KC + br + 16 * i) * NCOLS +
                                         4 * bc);
        }
        __syncthreads();

        // ---- MMA on this stage: 2 fp16 passes (Ah*Bh + Ah*Bl), fp32 acc ----
        const uint32_t sa = sb + (c & 1) * STAGE_B;
        #pragma unroll
        for (int ki = 0; ki < 2; ki++) {
            const uint32_t a_off =
                (uint32_t)((wm * 64 + (lane & 15)) * A_ROW_B + (ki * 16 + (lane >> 4) * 8) * 2);
            const uint32_t b_off =
                (uint32_t)((ki * 16 + (lane & 15)) * B_ROW_B + wn * 64);

            uint32_t Ah[4][4], Bh[4][2], Bl[4][2];
            #pragma unroll
            for (int mi = 0; mi < 4; mi++)
                ldm_x4(Ah[mi], sa + OFF_A_HI + a_off + mi * 16 * A_ROW_B);
            #pragma unroll
            for (int nj = 0; nj < 4; nj++)
                ldm_x2t(Bh[nj], sa + OFF_B_HI + b_off + nj * 16);
            #pragma unroll
            for (int nj = 0; nj < 4; nj++)
                ldm_x2t(Bl[nj], sa + OFF_B_LO + b_off + nj * 16);

            #pragma unroll
            for (int mi = 0; mi < 4; mi++)
                #pragma unroll
                for (int nj = 0; nj < 4; nj++)
                    mma_f16(acc[mi][nj], Ah[mi], Bh[nj]);   // Ah x Bh
            #pragma unroll
            for (int mi = 0; mi < 4; mi++)
                #pragma unroll
                for (int nj = 0; nj < 4; nj++)
                    mma_f16(acc[mi][nj], Ah[mi], Bl[nj]);   // Ah x Bl
        }
    }

    // ---- epilogue: registers -> global ----
    const int r0 = b * BLK + wm * 64 + (lane >> 2);
    const int c0 = nt * BN + wn * 32 + (lane & 3) * 2;
    #pragma unroll
    for (int mi = 0; mi < 4; mi++)
        #pragma unroll
        for (int nj = 0; nj < 4; nj++) {
            float2 v0; v0.x = acc[mi][nj][0]; v0.y = acc[mi][nj][1];
            float2 v1; v1.x = acc[mi][nj][2]; v1.y = acc[mi][nj][3];
            const size_t base = (size_t)(r0 + mi * 16) * NCOLS + (size_t)(c0 + nj * 8);
            *(float2*)(out + base) = v0;
            *(float2*)(out + base + (size_t)8 * NCOLS) = v1;
        }
}

// ---------------- launch ----------------
extern "C" void kernel_launch(void* const* d_in, const int* in_sizes, int n_in,
                              void* d_out, int out_size) {
    const float* X = (const float*)d_in[0];   // inp [4096, 8192]
    const float* W = (const float*)d_in[1];   // W   [16, 256, 256]
    float* out = (float*)d_out;

    cudaFuncSetAttribute(blk_gemm, cudaFuncAttributeMaxDynamicSharedMemorySize, SMEM_TOTAL);

    dim3 grid(NBLK * (NCOLS / BN));   // 16 * 64 = 1024
    blk_gemm<<<grid, 512, SMEM_TOTAL>>>(X, W, out);
}

// round 4
// speedup vs baseline: 1.2479x; 1.0503x over previous
#include <cuda_runtime.h>
#include <cuda_fp16.h>
#include <cstdint>

// ---------------- problem constants ----------------
#define NCOLS 8192
#define BLK   256
#define NBLK  16

// ---------------- tile config ----------------
#define BN 128      // output cols per CTA
#define KC 32       // K chunk
#define NCHUNK 8    // 256/32

// ---------------- SMEM layout ----------------
// A: whole W block as fp16: 256 rows x (256 fp16 = 512B + 16B pad) = 528B/row
// B: two stages, 32 rows x (128 fp16 = 256B + 16B pad) = 272B/row
#define A_ROW 528
#define OFF_B (256 * A_ROW)          // 135168
#define B_ROW 272
#define B_STAGE (32 * B_ROW)         // 8704
#define SMEM_TOTAL (OFF_B + 2 * B_STAGE)   // 152576

// ---------------- helpers ----------------
__device__ __forceinline__ uint32_t smem_u32(const void* p) {
    uint32_t a;
    asm("{ .reg .u64 t; cvta.to.shared.u64 t, %1; cvt.u32.u64 %0, t; }" : "=r"(a) : "l"(p));
    return a;
}

// pack two fp32 -> fp16x2 (x0 in low half)
__device__ __forceinline__ uint32_t cvt_f16x2(float x0, float x1) {
    uint32_t r;
    asm("cvt.rn.f16x2.f32 %0, %1, %2;" : "=r"(r) : "f"(x1), "f"(x0));
    return r;
}

__device__ __forceinline__ void ldm_x4(uint32_t (&r)[4], uint32_t addr) {
    asm volatile("ldmatrix.sync.aligned.m8n8.x4.shared.b16 {%0,%1,%2,%3}, [%4];"
                 : "=r"(r[0]), "=r"(r[1]), "=r"(r[2]), "=r"(r[3]) : "r"(addr));
}

__device__ __forceinline__ void ldm_x2t(uint32_t (&r)[2], uint32_t addr) {
    asm volatile("ldmatrix.sync.aligned.m8n8.x2.trans.shared.b16 {%0,%1}, [%2];"
                 : "=r"(r[0]), "=r"(r[1]) : "r"(addr));
}

__device__ __forceinline__ void mma_f16(float (&d)[4], const uint32_t (&a)[4],
                                        const uint32_t (&b)[2]) {
    asm volatile(
        "mma.sync.aligned.m16n8k16.row.col.f32.f16.f16.f32 "
        "{%0,%1,%2,%3}, {%4,%5,%6,%7}, {%8,%9}, {%0,%1,%2,%3};"
        : "+f"(d[0]), "+f"(d[1]), "+f"(d[2]), "+f"(d[3])
        : "r"(a[0]), "r"(a[1]), "r"(a[2]), "r"(a[3]), "r"(b[0]), "r"(b[1]));
}

// ---------------- kernel ----------------
__global__ void __launch_bounds__(512, 1)
blk_gemm(const float* __restrict__ X,   // [4096, 8192]
         const float* __restrict__ W,   // [16, 256, 256]
         float* __restrict__ out)       // [4096, 8192]
{
    extern __shared__ char smem[];
    const uint32_t sb = smem_u32(smem);
    const int tid  = threadIdx.x;
    const int lane = tid & 31;
    const int w    = tid >> 5;     // 0..15
    const int wm   = w & 3;        // M quadrant (64 rows)
    const int wn   = w >> 2;       // N quarter  (32 cols)
    const int b    = blockIdx.x >> 6;
    const int nt   = blockIdx.x & 63;

    const float* Xb = X + (size_t)b * BLK * NCOLS + (size_t)nt * BN;
    const float* Wb = W + (size_t)b * (BLK * BLK);

    float acc[4][4][4];
    #pragma unroll
    for (int mi = 0; mi < 4; mi++)
        #pragma unroll
        for (int nj = 0; nj < 4; nj++)
            #pragma unroll
            for (int q = 0; q < 4; q++) acc[mi][nj][q] = 0.f;

    // ---- prologue: convert ENTIRE W block to fp16 in SMEM (once) ----
    {
        const float2* Wb2 = (const float2*)Wb;   // 32768 float2
        #pragma unroll 4
        for (int i = 0; i < 64; i++) {
            const int idx  = tid + 512 * i;
            const int row  = idx >> 7;        // 128 float2 per row
            const int col2 = idx & 127;
            float2 v = Wb2[idx];
            *(uint32_t*)(smem + row * A_ROW + col2 * 4) = cvt_f16x2(v.x, v.y);
        }
    }

    // ---- B pipeline prologue ----
    const int br = tid >> 5;   // row 0..15 (+16)
    const int bc = tid & 31;   // float4 col
    float4 bR[2];
    // chunk 0 -> regs
    #pragma unroll
    for (int i = 0; i < 2; i++)
        bR[i] = *(const float4*)(Xb + (size_t)(br + 16 * i) * NCOLS + 4 * bc);
    // store chunk 0 -> stage 0
    #pragma unroll
    for (int i = 0; i < 2; i++) {
        uint2 hv;
        hv.x = cvt_f16x2(bR[i].x, bR[i].y);
        hv.y = cvt_f16x2(bR[i].z, bR[i].w);
        *(uint2*)(smem + OFF_B + (br + 16 * i) * B_ROW + bc * 8) = hv;
    }
    // prefetch chunk 1 -> regs
    #pragma unroll
    for (int i = 0; i < 2; i++)
        bR[i] = *(const float4*)(Xb + (size_t)(KC + br + 16 * i) * NCOLS + 4 * bc);
    __syncthreads();

    // ---- main loop: one barrier per chunk; STS/LDG overlapped with MMA ----
    for (int c = 0; c < NCHUNK; c++) {
        const uint32_t sBr = sb + OFF_B + (c & 1) * B_STAGE;          // read stage
        char* const    pBw = smem + OFF_B + ((c + 1) & 1) * B_STAGE;  // write stage

        #pragma unroll
        for (int ki = 0; ki < 2; ki++) {
            const uint32_t a_off =
                (uint32_t)((wm * 64 + (lane & 15)) * A_ROW +
                           c * 64 + ki * 32 + (lane >> 4) * 16);
            const uint32_t b_off =
                (uint32_t)((ki * 16 + (lane & 15)) * B_ROW + wn * 64);

            uint32_t Ah[4][4], Bh[4][2];
            #pragma unroll
            for (int mi = 0; mi < 4; mi++)
                ldm_x4(Ah[mi], sb + a_off + mi * 16 * A_ROW);
            #pragma unroll
            for (int nj = 0; nj < 4; nj++)
                ldm_x2t(Bh[nj], sBr + b_off + nj * 16);

            // overlapped B pipeline work (independent of MMA below)
            if (ki == 0 && c < NCHUNK - 1) {
                #pragma unroll
                for (int i = 0; i < 2; i++) {
                    uint2 hv;
                    hv.x = cvt_f16x2(bR[i].x, bR[i].y);
                    hv.y = cvt_f16x2(bR[i].z, bR[i].w);
                    *(uint2*)(pBw + (br + 16 * i) * B_ROW + bc * 8) = hv;
                }
            }
            if (ki == 1 && c < NCHUNK - 2) {
                #pragma unroll
                for (int i = 0; i < 2; i++)
                    bR[i] = *(const float4*)(Xb + (size_t)((c + 2) * KC + br + 16 * i) * NCOLS +
                                             4 * bc);
            }

            #pragma unroll
            for (int mi = 0; mi < 4; mi++)
                #pragma unroll
                for (int nj = 0; nj < 4; nj++)
                    mma_f16(acc[mi][nj], Ah[mi], Bh[nj]);
        }
        __syncthreads();
    }

    // ---- epilogue: registers -> global ----
    const int r0 = b * BLK + wm * 64 + (lane >> 2);
    const int c0 = nt * BN + wn * 32 + (lane & 3) * 2;
    #pragma unroll
    for (int mi = 0; mi < 4; mi++)
        #pragma unroll
        for (int nj = 0; nj < 4; nj++) {
            float2 v0; v0.x = acc[mi][nj][0]; v0.y = acc[mi][nj][1];
            float2 v1; v1.x = acc[mi][nj][2]; v1.y = acc[mi][nj][3];
            const size_t base = (size_t)(r0 + mi * 16) * NCOLS + (size_t)(c0 + nj * 8);
            *(float2*)(out + base) = v0;
            *(float2*)(out + base + (size_t)8 * NCOLS) = v1;
        }
}

// ---------------- launch ----------------
extern "C" void kernel_launch(void* const* d_in, const int* in_sizes, int n_in,
                              void* d_out, int out_size) {
    const float* X = (const float*)d_in[0];   // inp [4096, 8192]
    const float* W = (const float*)d_in[1];   // W   [16, 256, 256]
    float* out = (float*)d_out;

    cudaFuncSetAttribute(blk_gemm, cudaFuncAttributeMaxDynamicSharedMemorySize, SMEM_TOTAL);

    dim3 grid(NBLK * (NCOLS / BN));   // 16 * 64 = 1024
    blk_gemm<<<grid, 512, SMEM_TOTAL>>>(X, W, out);
}